// round 16
// baseline (speedup 1.0000x reference)
#include <cuda_runtime.h>
#include <stdint.h>
#include <math.h>

#define B_ 8
#define S_ 2048
#define DSTATE 1024
#define H_ 16
#define DH_ 64
#define PROJW 4096
#define M_ (B_ * S_)   // 16384

typedef unsigned long long u64;

// Scratch (device globals: allocation-free, graph-capturable)
__device__ float g_proj[(size_t)M_ * PROJW];   // 256 MB
__device__ float g_hseq[(size_t)M_ * DSTATE];  // 64 MB
__device__ float g_y[(size_t)M_ * DSTATE];     // 64 MB

__device__ __forceinline__ float* sel_buf(int s, const void* ext) {
    switch (s) {
        case 1: return g_proj;
        case 2: return g_hseq;
        case 3: return g_y;
        default: return (float*)ext;
    }
}

// Packed 2-wide fp32 FMA (Blackwell FFMA2; ptxas never auto-emits it)
#define FMA2(d, a, b) \
    asm("fma.rn.f32x2 %0, %1, %2, %0;" : "+l"(d) : "l"(a), "l"(b))
#define DUP2(d, s) \
    asm("mov.b64 %0, {%1, %1};" : "=l"(d) : "r"(s))
#define PACK2(d, lo, hi) \
    asm("mov.b64 %0, {%1, %2};" : "=l"(d) : "r"(lo), "r"(hi))

// Branch-free MUFU transcendentals (serial-path critical in the recurrence)
__device__ __forceinline__ float fast_sigmoid(float x) {
    float e;
    asm("ex2.approx.f32 %0, %1;" : "=f"(e) : "f"(-x * 1.442695041f));
    float r;
    asm("rcp.approx.f32 %0, %1;" : "=f"(r) : "f"(e + 1.f));
    return r;
}
__device__ __forceinline__ float fast_tanh(float x) {
    // tanh(x) = 1 - 2/(exp(2x)+1); exact at both saturations
    float e;
    asm("ex2.approx.f32 %0, %1;" : "=f"(e) : "f"(x * 2.885390082f));
    float r;
    asm("rcp.approx.f32 %0, %1;" : "=f"(r) : "f"(e + 1.f));
    return fmaf(-2.f, r, 1.f);
}

// ---------------------------------------------------------------------------
// GEMM: C[M,N] = A[M,K] @ B[K,N], row-major. 128x128 tile, BK=16 (barriers
// amortized 2x vs R13), 256 thr, 8x8 microtile via f32x2, conflict-free
// split B fragments, double-buffered smem, register prefetch, 2 CTAs/SM.
// ---------------------------------------------------------------------------
__global__ __launch_bounds__(256, 2) void gemm128(const void* Aext, int a_sel,
                                                  const float* __restrict__ Bm,
                                                  void* Cext, int c_sel,
                                                  int M, int N, int K)
{
    const float* __restrict__ A = sel_buf(a_sel, Aext);
    float* __restrict__ C = sel_buf(c_sel, Cext);

    __shared__ float As[2][16][128];
    __shared__ float Bs[2][16][128];

    const int tid = threadIdx.x;
    const int bm = blockIdx.y * 128;
    const int bn = blockIdx.x * 128;
    const int tx = tid & 15;   // cols: tx*4..+3 and 64+tx*4..+3
    const int ty = tid >> 4;   // rows: ty*8..+7

    u64 acc2[8][4] = {};

    const int am = tid >> 1;          // 0..127
    const int ak = (tid & 1) * 4;     // 0 or 4 (plus +8 twin)
    const int bk  = tid >> 5;         // 0..7  (plus +8 twin)
    const int bn4 = (tid & 31) * 4;

    const float* Aptr = A + (size_t)(bm + am) * K + ak;
    const float* Bptr = Bm + (size_t)bk * N + bn + bn4;

    float4 av0 = *(const float4*)(Aptr);
    float4 av1 = *(const float4*)(Aptr + 8);
    float4 bv0 = *(const float4*)(Bptr);
    float4 bv1 = *(const float4*)(Bptr + (size_t)8 * N);

    int buf = 0;
    for (int k0 = 0; k0 < K; k0 += 16) {
        As[buf][ak + 0][am] = av0.x;
        As[buf][ak + 1][am] = av0.y;
        As[buf][ak + 2][am] = av0.z;
        As[buf][ak + 3][am] = av0.w;
        As[buf][ak + 8][am] = av1.x;
        As[buf][ak + 9][am] = av1.y;
        As[buf][ak + 10][am] = av1.z;
        As[buf][ak + 11][am] = av1.w;
        *(float4*)&Bs[buf][bk][bn4]     = bv0;
        *(float4*)&Bs[buf][bk + 8][bn4] = bv1;
        __syncthreads();

        if (k0 + 16 < K) {
            av0 = *(const float4*)(Aptr + k0 + 16);
            av1 = *(const float4*)(Aptr + k0 + 24);
            bv0 = *(const float4*)(Bptr + (size_t)(k0 + 16) * N);
            bv1 = *(const float4*)(Bptr + (size_t)(k0 + 24) * N);
        }

#pragma unroll
        for (int k = 0; k < 16; k++) {
            uint4 aa0 = *(const uint4*)&As[buf][k][ty * 8];       // broadcast
            uint4 aa1 = *(const uint4*)&As[buf][k][ty * 8 + 4];
            ulonglong2 bb0 = *(const ulonglong2*)&Bs[buf][k][tx * 4];       // contiguous
            ulonglong2 bb1 = *(const ulonglong2*)&Bs[buf][k][64 + tx * 4];  // contiguous

            u64 a2[8], b2[4];
            DUP2(a2[0], aa0.x); DUP2(a2[1], aa0.y);
            DUP2(a2[2], aa0.z); DUP2(a2[3], aa0.w);
            DUP2(a2[4], aa1.x); DUP2(a2[5], aa1.y);
            DUP2(a2[6], aa1.z); DUP2(a2[7], aa1.w);
            b2[0] = bb0.x; b2[1] = bb0.y; b2[2] = bb1.x; b2[3] = bb1.y;

#pragma unroll
            for (int i = 0; i < 8; i++)
#pragma unroll
                for (int j2 = 0; j2 < 4; j2++)
                    FMA2(acc2[i][j2], a2[i], b2[j2]);
        }
        buf ^= 1;
    }

#pragma unroll
    for (int i = 0; i < 8; i++) {
        float2 p0 = *(float2*)&acc2[i][0];
        float2 p1 = *(float2*)&acc2[i][1];
        float2 p2 = *(float2*)&acc2[i][2];
        float2 p3 = *(float2*)&acc2[i][3];
        float* Crow = C + (size_t)(bm + ty * 8 + i) * N + bn;
        *(float4*)(Crow + tx * 4)      = make_float4(p0.x, p0.y, p1.x, p1.y);
        *(float4*)(Crow + 64 + tx * 4) = make_float4(p2.x, p2.y, p3.x, p3.y);
    }
}

// ---------------------------------------------------------------------------
// Recurrence: one block per (b, h), 64 threads, hs duplicated ((v,v) pairs),
// 4 FFMA2 chains per phase, x prefetch depth 3, branch-free MUFU sigmoid/tanh.
// ---------------------------------------------------------------------------
__global__ __launch_bounds__(64, 1) void recur_kernel(const float* __restrict__ Wall)
{
    __shared__ float hs2[128];   // duplicated: hs2[2d] = hs2[2d+1] = h[d]
    __shared__ float rh[64];

    const int b = blockIdx.x >> 4;
    const int h = blockIdx.x & 15;
    const int e = threadIdx.x;

    u64 wrf[64];   // (Wr[d][e], Wf[d][e])
    u64 wc2[32];   // (Wc[2j][e], Wc[2j+1][e])
    {
        const float* Wc = Wall + (size_t)h * 4096 + e;
        const float* Wf = Wall + (size_t)(16 + h) * 4096 + e;
        const float* Wr = Wall + (size_t)(32 + h) * 4096 + e;
#pragma unroll
        for (int d = 0; d < 64; d++)
            PACK2(wrf[d], __float_as_uint(Wr[d * 64]), __float_as_uint(Wf[d * 64]));
#pragma unroll
        for (int j = 0; j < 32; j++)
            PACK2(wc2[j], __float_as_uint(Wc[2 * j * 64]), __float_as_uint(Wc[(2 * j + 1) * 64]));
    }

    hs2[2 * e] = 0.f; hs2[2 * e + 1] = 0.f;
    float hprev = 0.f;
    __syncthreads();

    const float* xp = g_proj + (size_t)b * S_ * PROJW + h * DH_ + e;
    float* op = g_hseq + (size_t)b * S_ * DSTATE + h * DH_ + e;

    // prefetch pipeline: cur = x[t], +1, +2
    float xi = xp[0],        xf = xp[1024],        xr = xp[2048];
    float i0 = xp[PROJW],     f0 = xp[PROJW + 1024], r0 = xp[PROJW + 2048];
    float i1 = xp[2 * PROJW], f1 = xp[2 * PROJW + 1024], r1 = xp[2 * PROJW + 2048];

    for (int t = 0; t < S_; t++) {
        float ni = 0.f, nf = 0.f, nr = 0.f;
        if (t + 3 < S_) {
            const float* xq = xp + 3 * PROJW;
            ni = xq[0]; nf = xq[1024]; nr = xq[2048];
        }
        xp += PROJW;

        u64 arf0 = 0, arf1 = 0, arf2 = 0, arf3 = 0;  // 4 chains, lanes (r,f)
#pragma unroll
        for (int d4 = 0; d4 < 64; d4 += 4) {
            ulonglong2 hd01 = *(const ulonglong2*)&hs2[2 * d4];
            ulonglong2 hd23 = *(const ulonglong2*)&hs2[2 * d4 + 4];
            FMA2(arf0, hd01.x, wrf[d4 + 0]);
            FMA2(arf1, hd01.y, wrf[d4 + 1]);
            FMA2(arf2, hd23.x, wrf[d4 + 2]);
            FMA2(arf3, hd23.y, wrf[d4 + 3]);
        }
        float2 s0 = *(float2*)&arf0;
        float2 s1 = *(float2*)&arf1;
        float2 s2 = *(float2*)&arf2;
        float2 s3 = *(float2*)&arf3;
        float r = fast_sigmoid(xr + (s0.x + s1.x) + (s2.x + s3.x));
        float f = fast_sigmoid(xf + (s0.y + s1.y) + (s2.y + s3.y));
        rh[e] = r * hprev;
        __syncthreads();   // rh visible; all hs2 reads of this step done

        u64 ac0 = 0, ac1 = 0, ac2 = 0, ac3 = 0;
#pragma unroll
        for (int d8 = 0; d8 < 64; d8 += 8) {
            ulonglong2 rv0 = *(const ulonglong2*)&rh[d8];
            ulonglong2 rv1 = *(const ulonglong2*)&rh[d8 + 4];
            FMA2(ac0, rv0.x, wc2[d8 / 2 + 0]);
            FMA2(ac1, rv0.y, wc2[d8 / 2 + 1]);
            FMA2(ac2, rv1.x, wc2[d8 / 2 + 2]);
            FMA2(ac3, rv1.y, wc2[d8 / 2 + 3]);
        }
        float2 c0 = *(float2*)&ac0;
        float2 c1 = *(float2*)&ac1;
        float2 c2 = *(float2*)&ac2;
        float2 c3 = *(float2*)&ac3;
        float c = fast_tanh(xi + (c0.x + c0.y) + (c1.x + c1.y) + (c2.x + c2.y) + (c3.x + c3.y));
        float hnew = f * hprev + (1.f - f) * c;

        *(float2*)&hs2[2 * e] = make_float2(hnew, hnew);  // safe: reads done pre-bar
        hprev = hnew;
        *op = hnew;
        op += DSTATE;

        xi = i0; xf = f0; xr = r0;
        i0 = i1; f0 = f1; r0 = r1;
        i1 = ni; f1 = nf; r1 = nr;
        __syncthreads();   // hs2 update visible before next step
    }
}

// ---------------------------------------------------------------------------
// Gated SiLU + RMSNorm (proven)
// ---------------------------------------------------------------------------
__global__ __launch_bounds__(256) void gate_norm_kernel(const float* __restrict__ nw)
{
    const int row = blockIdx.x;
    const float* g    = g_proj + (size_t)row * PROJW + 3072;
    const float* hrow = g_hseq + (size_t)row * DSTATE;
    float* yrow = g_y + (size_t)row * DSTATE;
    const int tid = threadIdx.x;

    float v[4];
    float ss = 0.f;
#pragma unroll
    for (int i = 0; i < 4; i++) {
        int c = tid + i * 256;
        float gv = g[c];
        float hv = hrow[c];
        float yv = hv * gv * fast_sigmoid(gv);
        v[i] = yv;
        ss += yv * yv;
    }

    __shared__ float red[8];
#pragma unroll
    for (int o = 16; o; o >>= 1) ss += __shfl_xor_sync(0xffffffffu, ss, o);
    if ((tid & 31) == 0) red[tid >> 5] = ss;
    __syncthreads();
    if (tid < 8) {
        float s = red[tid];
#pragma unroll
        for (int o = 4; o; o >>= 1) s += __shfl_xor_sync(0xffu, s, o);
        if (tid == 0) red[0] = s;
    }
    __syncthreads();
    const float scale = rsqrtf(red[0] * (1.f / 1024.f) + 1e-6f);

#pragma unroll
    for (int i = 0; i < 4; i++) {
        int c = tid + i * 256;
        yrow[c] = v[i] * scale * nw[c];
    }
}

// ---------------------------------------------------------------------------
// Launch — kernel launches ONLY.
// ---------------------------------------------------------------------------
extern "C" void kernel_launch(void* const* d_in, const int* in_sizes, int n_in,
                              void* d_out, int out_size)
{
    const float* x      = (const float*)d_in[0];  // [8,2048,1024]
    const float* w_in   = (const float*)d_in[1];  // [1024,4096]
    const float* s_w    = (const float*)d_in[2];  // [48,64,64]
    const float* norm_w = (const float*)d_in[3];  // [1024]
    const float* w_out  = (const float*)d_in[4];  // [1024,1024]

    // 1) input projection: x[16384,1024] @ w_in[1024,4096] -> g_proj
    {
        dim3 grid(PROJW / 128, M_ / 128);
        gemm128<<<grid, 256>>>(x, 0, w_in, nullptr, 1, M_, PROJW, 1024);
    }

    // 2) recurrence -> g_hseq
    recur_kernel<<<B_ * H_, 64>>>(s_w);

    // 3) gated silu + rmsnorm -> g_y
    gate_norm_kernel<<<M_, 256>>>(norm_w);

    // 4) output projection: g_y[16384,1024] @ w_out[1024,1024] -> d_out
    {
        dim3 grid(1024 / 128, M_ / 128);
        gemm128<<<grid, 256>>>(nullptr, 3, w_out, d_out, 0, M_, 1024, 1024);
    }
}

// round 17
// speedup vs baseline: 1.1910x; 1.1910x over previous
#include <cuda_runtime.h>
#include <stdint.h>
#include <math.h>

#define B_ 8
#define S_ 2048
#define DSTATE 1024
#define H_ 16
#define DH_ 64
#define PROJW 4096
#define M_ (B_ * S_)   // 16384

typedef unsigned long long u64;

// Scratch (device globals: allocation-free, graph-capturable)
__device__ float g_proj[(size_t)M_ * PROJW];   // 256 MB
__device__ float g_hseq[(size_t)M_ * DSTATE];  // 64 MB
__device__ float g_y[(size_t)M_ * DSTATE];     // 64 MB

__device__ __forceinline__ float* sel_buf(int s, const void* ext) {
    switch (s) {
        case 1: return g_proj;
        case 2: return g_hseq;
        case 3: return g_y;
        default: return (float*)ext;
    }
}

// Packed 2-wide fp32 FMA (Blackwell FFMA2; ptxas never auto-emits it)
#define FMA2(d, a, b) \
    asm("fma.rn.f32x2 %0, %1, %2, %0;" : "+l"(d) : "l"(a), "l"(b))
#define DUP2(d, s) \
    asm("mov.b64 %0, {%1, %1};" : "=l"(d) : "r"(s))
#define PACK2(d, lo, hi) \
    asm("mov.b64 %0, {%1, %2};" : "=l"(d) : "r"(lo), "r"(hi))
// Named barrier for the 64 working recurrence threads (others have exited)
#define BAR64() asm volatile("bar.sync 1, 64;" ::: "memory")

// ---------------------------------------------------------------------------
// GEMM (exact R13/R15 WIN version): C[M,N] = A[M,K] @ B[K,N]. 128x128 tile,
// BK=8, 256 thr, 8x8 microtile via f32x2, conflict-free split B fragments,
// double-buffered smem, register prefetch, 2 CTAs/SM.
// NOTE: grid.x may cover only a prefix of N (N stays the row stride).
// ---------------------------------------------------------------------------
__global__ __launch_bounds__(256, 2) void gemm128(const void* Aext, int a_sel,
                                                  const float* __restrict__ Bm,
                                                  void* Cext, int c_sel,
                                                  int M, int N, int K)
{
    const float* __restrict__ A = sel_buf(a_sel, Aext);
    float* __restrict__ C = sel_buf(c_sel, Cext);

    __shared__ float As[2][8][128];
    __shared__ float Bs[2][8][128];

    const int tid = threadIdx.x;
    const int bm = blockIdx.y * 128;
    const int bn = blockIdx.x * 128;
    const int tx = tid & 15;
    const int ty = tid >> 4;

    u64 acc2[8][4] = {};

    const int am = tid >> 1;
    const int ak = (tid & 1) * 4;
    const int bk  = tid >> 5;
    const int bn4 = (tid & 31) * 4;

    const float* Aptr = A + (size_t)(bm + am) * K + ak;
    const float* Bptr = Bm + (size_t)bk * N + bn + bn4;

    float4 av = *(const float4*)(Aptr);
    float4 bv = *(const float4*)(Bptr);

    int buf = 0;
    for (int k0 = 0; k0 < K; k0 += 8) {
        As[buf][ak + 0][am] = av.x;
        As[buf][ak + 1][am] = av.y;
        As[buf][ak + 2][am] = av.z;
        As[buf][ak + 3][am] = av.w;
        *(float4*)&Bs[buf][bk][bn4] = bv;
        __syncthreads();

        if (k0 + 8 < K) {
            av = *(const float4*)(Aptr + k0 + 8);
            bv = *(const float4*)(Bptr + (size_t)(k0 + 8) * N);
        }

#pragma unroll
        for (int k = 0; k < 8; k++) {
            uint4 aa0 = *(const uint4*)&As[buf][k][ty * 8];
            uint4 aa1 = *(const uint4*)&As[buf][k][ty * 8 + 4];
            ulonglong2 bb0 = *(const ulonglong2*)&Bs[buf][k][tx * 4];
            ulonglong2 bb1 = *(const ulonglong2*)&Bs[buf][k][64 + tx * 4];

            u64 a2[8], b2[4];
            DUP2(a2[0], aa0.x); DUP2(a2[1], aa0.y);
            DUP2(a2[2], aa0.z); DUP2(a2[3], aa0.w);
            DUP2(a2[4], aa1.x); DUP2(a2[5], aa1.y);
            DUP2(a2[6], aa1.z); DUP2(a2[7], aa1.w);
            b2[0] = bb0.x; b2[1] = bb0.y; b2[2] = bb1.x; b2[3] = bb1.y;

#pragma unroll
            for (int i = 0; i < 8; i++)
#pragma unroll
                for (int j2 = 0; j2 < 4; j2++)
                    FMA2(acc2[i][j2], a2[i], b2[j2]);
        }
        buf ^= 1;
    }

#pragma unroll
    for (int i = 0; i < 8; i++) {
        float2 p0 = *(float2*)&acc2[i][0];
        float2 p1 = *(float2*)&acc2[i][1];
        float2 p2 = *(float2*)&acc2[i][2];
        float2 p3 = *(float2*)&acc2[i][3];
        float* Crow = C + (size_t)(bm + ty * 8 + i) * N + bn;
        *(float4*)(Crow + tx * 4)      = make_float4(p0.x, p0.y, p1.x, p1.y);
        *(float4*)(Crow + 64 + tx * 4) = make_float4(p2.x, p2.y, p3.x, p3.y);
    }
}

// ---------------------------------------------------------------------------
// FUSED kernel: blocks [0,128) run the recurrence (R15 version, 64 working
// threads, named barriers); blocks [128, 128+2048) run the GATE GEMM
// (g_proj cols 3072..4095 = x @ w_in[:,3072:]) as 128-thread 128x64-tile
// CTAs that fill the SMs left idle by the latency-bound recurrence.
// ---------------------------------------------------------------------------
#define NREC 128
#define GATE_TILES 2048   // 128 m-tiles x 16 n-tiles (64-wide)

__global__ __launch_bounds__(128) void fused_recur_gate(
    const float* __restrict__ x,
    const float* __restrict__ w_in,
    const float* __restrict__ Wall)
{
    if (blockIdx.x < NREC) {
        // ================= recurrence (R15) =================
        __shared__ float hs2[128];
        __shared__ float rh[64];

        const int e = threadIdx.x;
        if (e >= 64) return;            // extra threads exit (named bar below)

        const int b = blockIdx.x >> 4;
        const int h = blockIdx.x & 15;

        u64 wrf[64];   // (Wr[d][e], Wf[d][e])
        u64 wc2[32];   // (Wc[2j][e], Wc[2j+1][e])
        {
            const float* Wc = Wall + (size_t)h * 4096 + e;
            const float* Wf = Wall + (size_t)(16 + h) * 4096 + e;
            const float* Wr = Wall + (size_t)(32 + h) * 4096 + e;
#pragma unroll
            for (int d = 0; d < 64; d++)
                PACK2(wrf[d], __float_as_uint(Wr[d * 64]), __float_as_uint(Wf[d * 64]));
#pragma unroll
            for (int j = 0; j < 32; j++)
                PACK2(wc2[j], __float_as_uint(Wc[2 * j * 64]), __float_as_uint(Wc[(2 * j + 1) * 64]));
        }

        hs2[2 * e] = 0.f; hs2[2 * e + 1] = 0.f;
        float hprev = 0.f;
        BAR64();

        const float* xp = g_proj + (size_t)b * S_ * PROJW + h * DH_ + e;
        float* op = g_hseq + (size_t)b * S_ * DSTATE + h * DH_ + e;

        float xi = xp[0],        xf = xp[1024],        xr = xp[2048];
        float i0 = xp[PROJW],     f0 = xp[PROJW + 1024], r0 = xp[PROJW + 2048];
        float i1 = xp[2 * PROJW], f1 = xp[2 * PROJW + 1024], r1 = xp[2 * PROJW + 2048];

        for (int t = 0; t < S_; t++) {
            float ni = 0.f, nf = 0.f, nr = 0.f;
            if (t + 3 < S_) {
                const float* xq = xp + 3 * PROJW;
                ni = xq[0]; nf = xq[1024]; nr = xq[2048];
            }
            xp += PROJW;

            u64 arf0 = 0, arf1 = 0, arf2 = 0, arf3 = 0;
#pragma unroll
            for (int d4 = 0; d4 < 64; d4 += 4) {
                ulonglong2 hd01 = *(const ulonglong2*)&hs2[2 * d4];
                ulonglong2 hd23 = *(const ulonglong2*)&hs2[2 * d4 + 4];
                FMA2(arf0, hd01.x, wrf[d4 + 0]);
                FMA2(arf1, hd01.y, wrf[d4 + 1]);
                FMA2(arf2, hd23.x, wrf[d4 + 2]);
                FMA2(arf3, hd23.y, wrf[d4 + 3]);
            }
            float2 s0 = *(float2*)&arf0;
            float2 s1 = *(float2*)&arf1;
            float2 s2 = *(float2*)&arf2;
            float2 s3 = *(float2*)&arf3;
            float r = 1.f / (1.f + __expf(-(xr + (s0.x + s1.x) + (s2.x + s3.x))));
            float f = 1.f / (1.f + __expf(-(xf + (s0.y + s1.y) + (s2.y + s3.y))));
            rh[e] = r * hprev;
            BAR64();

            u64 ac0 = 0, ac1 = 0, ac2 = 0, ac3 = 0;
#pragma unroll
            for (int d8 = 0; d8 < 64; d8 += 8) {
                ulonglong2 rv0 = *(const ulonglong2*)&rh[d8];
                ulonglong2 rv1 = *(const ulonglong2*)&rh[d8 + 4];
                FMA2(ac0, rv0.x, wc2[d8 / 2 + 0]);
                FMA2(ac1, rv0.y, wc2[d8 / 2 + 1]);
                FMA2(ac2, rv1.x, wc2[d8 / 2 + 2]);
                FMA2(ac3, rv1.y, wc2[d8 / 2 + 3]);
            }
            float2 c0 = *(float2*)&ac0;
            float2 c1 = *(float2*)&ac1;
            float2 c2 = *(float2*)&ac2;
            float2 c3 = *(float2*)&ac3;
            float c = tanhf(xi + (c0.x + c0.y) + (c1.x + c1.y) + (c2.x + c2.y) + (c3.x + c3.y));
            float hnew = f * hprev + (1.f - f) * c;

            *(float2*)&hs2[2 * e] = make_float2(hnew, hnew);
            hprev = hnew;
            *op = hnew;
            op += DSTATE;

            xi = i0; xf = f0; xr = r0;
            i0 = i1; f0 = f1; r0 = r1;
            i1 = ni; f1 = nf; r1 = nr;
            BAR64();
        }
        return;
    }

    // ================= gate GEMM: 128x64 tile, 128 threads =================
    {
        __shared__ float As[2][8][128];
        __shared__ float Bs[2][8][64];

        const int gid = blockIdx.x - NREC;     // 0..2047
        const int bm = (gid >> 4) * 128;
        const int bn = 3072 + (gid & 15) * 64;
        const int tid = threadIdx.x;
        const int tx = tid & 7;    // cols: tx*4..+3 and 32+tx*4..+3
        const int ty = tid >> 3;   // rows: ty*8..+7 (0..15)

        u64 acc2[8][4] = {};

        // A loader: 128x8 = 256 float4 / 128 thr = 2 each
        const int am = tid;                 // row pairs: rows tid and tid (2 kquads? no:)
        // idx mapping: idx = i*128 + tid; row = idx >> 1, kc = (idx & 1) * 4
        // B loader: 8x64 = 128 float4 / 128 thr = 1 each
        const int bbk = tid >> 4;           // 0..7
        const int bc4 = (tid & 15) * 4;     // 0..60

        const float* Bptr = w_in + (size_t)bbk * PROJW + bn + bc4;
        float4 bv = *(const float4*)(Bptr);
        float4 av0, av1;
        {
            int idx0 = tid, idx1 = 128 + tid;
            av0 = *(const float4*)(x + (size_t)(bm + (idx0 >> 1)) * 1024 + (idx0 & 1) * 4);
            av1 = *(const float4*)(x + (size_t)(bm + (idx1 >> 1)) * 1024 + (idx1 & 1) * 4);
        }

        int buf = 0;
        for (int k0 = 0; k0 < 1024; k0 += 8) {
            {
                int idx0 = tid, idx1 = 128 + tid;
                As[buf][(idx0 & 1) * 4 + 0][idx0 >> 1] = av0.x;
                As[buf][(idx0 & 1) * 4 + 1][idx0 >> 1] = av0.y;
                As[buf][(idx0 & 1) * 4 + 2][idx0 >> 1] = av0.z;
                As[buf][(idx0 & 1) * 4 + 3][idx0 >> 1] = av0.w;
                As[buf][(idx1 & 1) * 4 + 0][idx1 >> 1] = av1.x;
                As[buf][(idx1 & 1) * 4 + 1][idx1 >> 1] = av1.y;
                As[buf][(idx1 & 1) * 4 + 2][idx1 >> 1] = av1.z;
                As[buf][(idx1 & 1) * 4 + 3][idx1 >> 1] = av1.w;
                *(float4*)&Bs[buf][bbk][bc4] = bv;
            }
            __syncthreads();

            if (k0 + 8 < 1024) {
                int idx0 = tid, idx1 = 128 + tid;
                av0 = *(const float4*)(x + (size_t)(bm + (idx0 >> 1)) * 1024 + (idx0 & 1) * 4 + k0 + 8);
                av1 = *(const float4*)(x + (size_t)(bm + (idx1 >> 1)) * 1024 + (idx1 & 1) * 4 + k0 + 8);
                bv = *(const float4*)(Bptr + (size_t)(k0 + 8) * PROJW);
            }

#pragma unroll
            for (int k = 0; k < 8; k++) {
                uint4 aa0 = *(const uint4*)&As[buf][k][ty * 8];
                uint4 aa1 = *(const uint4*)&As[buf][k][ty * 8 + 4];
                ulonglong2 bb0 = *(const ulonglong2*)&Bs[buf][k][tx * 4];
                ulonglong2 bb1 = *(const ulonglong2*)&Bs[buf][k][32 + tx * 4];

                u64 a2[8], b2[4];
                DUP2(a2[0], aa0.x); DUP2(a2[1], aa0.y);
                DUP2(a2[2], aa0.z); DUP2(a2[3], aa0.w);
                DUP2(a2[4], aa1.x); DUP2(a2[5], aa1.y);
                DUP2(a2[6], aa1.z); DUP2(a2[7], aa1.w);
                b2[0] = bb0.x; b2[1] = bb0.y; b2[2] = bb1.x; b2[3] = bb1.y;

#pragma unroll
                for (int i = 0; i < 8; i++)
#pragma unroll
                    for (int j2 = 0; j2 < 4; j2++)
                        FMA2(acc2[i][j2], a2[i], b2[j2]);
            }
            buf ^= 1;
        }

#pragma unroll
        for (int i = 0; i < 8; i++) {
            float2 p0 = *(float2*)&acc2[i][0];
            float2 p1 = *(float2*)&acc2[i][1];
            float2 p2 = *(float2*)&acc2[i][2];
            float2 p3 = *(float2*)&acc2[i][3];
            float* Crow = g_proj + (size_t)(bm + ty * 8 + i) * PROJW + bn;
            *(float4*)(Crow + tx * 4)      = make_float4(p0.x, p0.y, p1.x, p1.y);
            *(float4*)(Crow + 32 + tx * 4) = make_float4(p2.x, p2.y, p3.x, p3.y);
        }
    }
}

// ---------------------------------------------------------------------------
// Gated SiLU + RMSNorm (proven)
// ---------------------------------------------------------------------------
__global__ __launch_bounds__(256) void gate_norm_kernel(const float* __restrict__ nw)
{
    const int row = blockIdx.x;
    const float* g    = g_proj + (size_t)row * PROJW + 3072;
    const float* hrow = g_hseq + (size_t)row * DSTATE;
    float* yrow = g_y + (size_t)row * DSTATE;
    const int tid = threadIdx.x;

    float v[4];
    float ss = 0.f;
#pragma unroll
    for (int i = 0; i < 4; i++) {
        int c = tid + i * 256;
        float gv = g[c];
        float hv = hrow[c];
        float yv = hv * gv / (1.f + __expf(-gv));
        v[i] = yv;
        ss += yv * yv;
    }

    __shared__ float red[8];
#pragma unroll
    for (int o = 16; o; o >>= 1) ss += __shfl_xor_sync(0xffffffffu, ss, o);
    if ((tid & 31) == 0) red[tid >> 5] = ss;
    __syncthreads();
    if (tid < 8) {
        float s = red[tid];
#pragma unroll
        for (int o = 4; o; o >>= 1) s += __shfl_xor_sync(0xffu, s, o);
        if (tid == 0) red[0] = s;
    }
    __syncthreads();
    const float scale = rsqrtf(red[0] * (1.f / 1024.f) + 1e-6f);

#pragma unroll
    for (int i = 0; i < 4; i++) {
        int c = tid + i * 256;
        yrow[c] = v[i] * scale * nw[c];
    }
}

// ---------------------------------------------------------------------------
// Launch — kernel launches ONLY.
// ---------------------------------------------------------------------------
extern "C" void kernel_launch(void* const* d_in, const int* in_sizes, int n_in,
                              void* d_out, int out_size)
{
    const float* x      = (const float*)d_in[0];  // [8,2048,1024]
    const float* w_in   = (const float*)d_in[1];  // [1024,4096]
    const float* s_w    = (const float*)d_in[2];  // [48,64,64]
    const float* norm_w = (const float*)d_in[3];  // [1024]
    const float* w_out  = (const float*)d_in[4];  // [1024,1024]

    // 1) input projection, recurrence columns only (0..3071): grid.x = 24
    {
        dim3 grid(3072 / 128, M_ / 128);
        gemm128<<<grid, 256>>>(x, 0, w_in, nullptr, 1, M_, PROJW, 1024);
    }

    // 2) FUSED: recurrence (blocks 0-127) + gate-column GEMM (blocks 128-2175)
    fused_recur_gate<<<NREC + GATE_TILES, 128>>>(x, w_in, s_w);

    // 3) gated silu + rmsnorm -> g_y
    gate_norm_kernel<<<M_, 256>>>(norm_w);

    // 4) output projection: g_y[16384,1024] @ w_out[1024,1024] -> d_out
    {
        dim3 grid(1024 / 128, M_ / 128);
        gemm128<<<grid, 256>>>(nullptr, 3, w_out, d_out, 0, M_, 1024, 1024);
    }
}